// round 13
// baseline (speedup 1.0000x reference)
#include <cuda_runtime.h>
#include <math.h>
#include <stdint.h>

// Problem constants
#define Bn   64
#define Cc   128
#define Hh   56
#define Ww   56
#define HW   3136            // Hh*Ww
#define NTOT 25690112        // Bn*Cc*HW
#define WN   147456          // Cc*Cc*9
#define NSTAT 200704         // Bn*HW
#define NC4  32              // Cc/4
#define FULLM 0xffffffffu
#define SP   60              // smem row pitch (floats/ints)

// ---------------- device scratch ----------------
__device__ float   g_qw1[WN];        // conv1 fp32 quantized weights [ci][k][co]
__device__ int     g_w2p[NC4*9*Cc];  // conv2 s8 weights packed [ci4][k][co][4]
__device__ float   g_y1[NTOT];       // conv1 raw output
__device__ int     g_a1p[NTOT/4];    // a1 int levels packed [n][ci4][h][w][4]
__device__ float   g_y2[NTOT];       // conv2 integer accumulator (exact in fp32)
__device__ double  g_sum[2][Cc];
__device__ double  g_sq[2][Cc];
__device__ float   g_mean[2][Cc];
__device__ float   g_rs[2][Cc];
__device__ unsigned g_maxbits[2];

// ---------------- packed f32x2 helpers ----------------
__device__ __forceinline__ unsigned long long pk2(float lo, float hi) {
    unsigned long long r;
    asm("mov.b64 %0, {%1, %2};" : "=l"(r)
        : "r"(__float_as_uint(lo)), "r"(__float_as_uint(hi)));
    return r;
}
__device__ __forceinline__ void upk2(unsigned long long v, float& lo, float& hi) {
    uint32_t a, b;
    asm("mov.b64 {%0, %1}, %2;" : "=r"(a), "=r"(b) : "l"(v));
    lo = __uint_as_float(a); hi = __uint_as_float(b);
}
__device__ __forceinline__ unsigned long long fma2(unsigned long long a,
                                                   unsigned long long b,
                                                   unsigned long long c) {
    unsigned long long d;
    asm("fma.rn.f32x2 %0, %1, %2, %3;" : "=l"(d) : "l"(a), "l"(b), "l"(c));
    return d;
}
__device__ __forceinline__ unsigned long long add2(unsigned long long a,
                                                   unsigned long long b) {
    unsigned long long d;
    asm("add.rn.f32x2 %0, %1, %2;" : "=l"(d) : "l"(a), "l"(b));
    return d;
}

// ---------------- math helpers ----------------
__device__ __forceinline__ float xla_tanh(float x) {
    if (fabsf(x) < 0.0004f) return x;
    float xc = fminf(fmaxf(x, -7.90531110763549805f), 7.90531110763549805f);
    float x2 = __fmul_rn(xc, xc);
    float np = -2.76076847742355e-16f;
    np = fmaf(np, x2, 2.00018790482477e-13f);
    np = fmaf(np, x2, -8.60467152213735e-11f);
    np = fmaf(np, x2, 5.12229709037114e-08f);
    np = fmaf(np, x2, 1.48572235717979e-05f);
    np = fmaf(np, x2, 6.37261928875436e-04f);
    np = fmaf(np, x2, 4.89352455891786e-03f);
    np = __fmul_rn(xc, np);
    float dp = 1.19825839466702e-06f;
    dp = fmaf(dp, x2, 1.18534705686654e-04f);
    dp = fmaf(dp, x2, 2.26843463243900e-03f);
    dp = fmaf(dp, x2, 4.89352518554385e-03f);
    return __fdiv_rn(np, dp);
}
__device__ __forceinline__ float ste_quant(float c) {
    float q = __fdiv_rn(rintf(__fmul_rn(c, 15.0f)), 15.0f);
    return __fadd_rn(c, __fadd_rn(q, -c));
}

// ---------------- kernels ----------------
__global__ void k_zero() {
    int i = threadIdx.x;
    if (i < Cc) { g_sum[0][i]=0.0; g_sum[1][i]=0.0; g_sq[0][i]=0.0; g_sq[1][i]=0.0; }
    if (i < 2) g_maxbits[i] = 0u;
}

__global__ void k_maxabs(const float* __restrict__ w1,
                         const float* __restrict__ w2) {
    const int t = blockIdx.y;
    const float* w = t ? w2 : w1;
    float m = 0.0f;
    for (int i = blockIdx.x * blockDim.x + threadIdx.x; i < WN;
         i += gridDim.x * blockDim.x)
        m = fmaxf(m, fabsf(xla_tanh(w[i])));
    #pragma unroll
    for (int o = 16; o; o >>= 1) m = fmaxf(m, __shfl_xor_sync(FULLM, m, o));
    if ((threadIdx.x & 31) == 0) atomicMax(&g_maxbits[t], __float_as_uint(m));
}

__global__ void k_quantw(const float* __restrict__ w1,
                         const float* __restrict__ w2) {
    const int t = blockIdx.y;
    const float* w = t ? w2 : w1;
    const float M = __uint_as_float(g_maxbits[t]);
    const float twoM = __fmul_rn(2.0f, M);
    for (int i = blockIdx.x * blockDim.x + threadIdx.x; i < WN;
         i += gridDim.x * blockDim.x) {
        float tv = xla_tanh(w[i]);
        float wn = __fadd_rn(__fdiv_rn(tv, twoM), 0.5f);
        int k = i % 9, ci = (i / 9) % Cc, co = i / (9 * Cc);
        if (t == 0) {
            float st = ste_quant(wn);
            float ov = __fadd_rn(__fmul_rn(2.0f, st), -1.0f);
            g_qw1[(ci * 9 + k) * Cc + co] = ov;
        } else {
            int lvl = (int)rintf(__fmul_rn(wn, 15.0f));
            signed char v = (signed char)(2 * lvl - 15);
            ((signed char*)g_w2p)[(((ci >> 2) * 9 + k) * Cc + co) * 4 + (ci & 3)] = v;
        }
    }
}

// ---------------------------------------------------------------------------
// conv1: fp32 direct 3x3, f32x2 packed FMAs, cascaded accumulation (4-ci).
// x slab (18 rows x 56 cols) staged in smem per ci (ping-pong, 1 sync/ci).
// Values entering the FMA sequence identical to R10 -> bit-identical y1.
// ---------------------------------------------------------------------------
#define TCO1 8
__global__ void __launch_bounds__(224, 2)
k_conv1(const float* __restrict__ xin) {
    __shared__ float sbuf[2][18 * SP];
    const float* __restrict__ wT = g_qw1;
    const int n   = blockIdx.z;
    const int co0 = blockIdx.y * TCO1;
    const int h0  = blockIdx.x * 16;
    const int h   = h0 + threadIdx.y;
    const int w0  = threadIdx.x * 4;
    const bool act = (h < Hh);
    const int tx  = threadIdx.x;
    const int ty  = threadIdx.y;
    const int tid = ty * 14 + tx;
    const int lane = tid & 31;

    const float* base = xin + (size_t)n * Cc * HW;

    // staging assignment: 252 float4 (18 rows x 14), thread does 1 or 2
    const int r0  = tid / 14,          cc0 = (tid % 14) * 4;
    const int gr0 = h0 - 1 + r0;
    const bool v0 = (gr0 >= 0) && (gr0 < Hh);
    const bool has1 = (tid < 28);
    const int r1  = (tid + 224) / 14,  cc1 = ((tid + 224) % 14) * 4;
    const int gr1 = h0 - 1 + r1;
    const bool v1 = has1 && (gr1 >= 0) && (gr1 < Hh);

    // preload ci = 0
    {
        float4 a = v0 ? __ldg((const float4*)(base + (size_t)gr0 * Ww + cc0))
                      : make_float4(0.f, 0.f, 0.f, 0.f);
        *(float4*)&sbuf[0][r0 * SP + cc0] = a;
        if (has1) {
            float4 b = v1 ? __ldg((const float4*)(base + (size_t)gr1 * Ww + cc1))
                          : make_float4(0.f, 0.f, 0.f, 0.f);
            *(float4*)&sbuf[0][r1 * SP + cc1] = b;
        }
    }
    __syncthreads();

    unsigned long long accm[4][4], acc2[4][4];
    #pragma unroll
    for (int cp = 0; cp < 4; cp++)
        #pragma unroll
        for (int j = 0; j < 4; j++) { accm[cp][j] = 0ull; acc2[cp][j] = 0ull; }

    #pragma unroll 1
    for (int ci = 0; ci < Cc; ci++) {
        const int p = ci & 1;
        float4 n0 = make_float4(0.f, 0.f, 0.f, 0.f);
        float4 n1 = make_float4(0.f, 0.f, 0.f, 0.f);
        if (ci < Cc - 1) {
            const float* ip = base + (size_t)(ci + 1) * HW;
            if (v0) n0 = __ldg((const float4*)(ip + (size_t)gr0 * Ww + cc0));
            if (v1) n1 = __ldg((const float4*)(ip + (size_t)gr1 * Ww + cc1));
        }

        float xv[3][6];
        #pragma unroll
        for (int r = 0; r < 3; r++) {
            const float* sp = &sbuf[p][(ty + r) * SP + w0];
            float4 m = *(const float4*)sp;
            xv[r][1] = m.x; xv[r][2] = m.y; xv[r][3] = m.z; xv[r][4] = m.w;
            xv[r][0] = (tx > 0)  ? sp[-1] : 0.0f;
            xv[r][5] = (tx < 13) ? sp[4]  : 0.0f;
        }
        unsigned long long xd[3][6];
        #pragma unroll
        for (int r = 0; r < 3; r++)
            #pragma unroll
            for (int c = 0; c < 6; c++)
                xd[r][c] = pk2(xv[r][c], xv[r][c]);

        const float* wp = wT + ci * 9 * Cc + co0;
        #pragma unroll
        for (int k = 0; k < 9; k++) {
            const int ky = k / 3, kx = k % 3;
            float4 wa = *(const float4*)(wp + k * Cc + 0);
            float4 wb = *(const float4*)(wp + k * Cc + 4);
            unsigned long long wpair[4];
            wpair[0] = pk2(wa.x, wa.y);
            wpair[1] = pk2(wa.z, wa.w);
            wpair[2] = pk2(wb.x, wb.y);
            wpair[3] = pk2(wb.z, wb.w);
            #pragma unroll
            for (int cp = 0; cp < 4; cp++)
                #pragma unroll
                for (int j = 0; j < 4; j++)
                    acc2[cp][j] = fma2(xd[ky][kx + j], wpair[cp], acc2[cp][j]);
        }
        if ((ci & 3) == 3) {
            #pragma unroll
            for (int cp = 0; cp < 4; cp++)
                #pragma unroll
                for (int j = 0; j < 4; j++) {
                    accm[cp][j] = add2(accm[cp][j], acc2[cp][j]);
                    acc2[cp][j] = 0ull;
                }
        }

        if (ci < Cc - 1) {
            *(float4*)&sbuf[p ^ 1][r0 * SP + cc0] = n0;
            if (has1) *(float4*)&sbuf[p ^ 1][r1 * SP + cc1] = n1;
        }
        __syncthreads();
    }

    float of[TCO1][4];
    #pragma unroll
    for (int cp = 0; cp < 4; cp++)
        #pragma unroll
        for (int j = 0; j < 4; j++)
            upk2(accm[cp][j], of[2 * cp][j], of[2 * cp + 1][j]);

    if (act) {
        #pragma unroll
        for (int c = 0; c < TCO1; c++) {
            float4 v = make_float4(of[c][0], of[c][1], of[c][2], of[c][3]);
            *(float4*)(g_y1 + (size_t)(n * Cc + co0 + c) * HW + h * Ww + w0) = v;
        }
    } else {
        #pragma unroll
        for (int c = 0; c < TCO1; c++)
            #pragma unroll
            for (int j = 0; j < 4; j++) of[c][j] = 0.f;
    }

    __shared__ double wsum[TCO1][7];
    __shared__ double wsq[TCO1][7];
    const int wrp = tid >> 5;
    #pragma unroll
    for (int c = 0; c < TCO1; c++) {
        double s = 0.0, q = 0.0;
        #pragma unroll
        for (int j = 0; j < 4; j++) {
            double v = (double)of[c][j];
            s += v; q += v * v;
        }
        #pragma unroll
        for (int o = 16; o; o >>= 1) {
            s += __shfl_down_sync(FULLM, s, o);
            q += __shfl_down_sync(FULLM, q, o);
        }
        if (lane == 0) { wsum[c][wrp] = s; wsq[c][wrp] = q; }
    }
    __syncthreads();
    if (tid < TCO1) {
        double s = 0.0, q = 0.0;
        #pragma unroll
        for (int k = 0; k < 7; k++) { s += wsum[tid][k]; q += wsq[tid][k]; }
        atomicAdd(&g_sum[0][co0 + tid], s);
        atomicAdd(&g_sq[0][co0 + tid], q);
    }
}

// ---------------------------------------------------------------------------
// conv2: EXACT int8 dp4a conv, same smem staging of the packed-int slab.
// ---------------------------------------------------------------------------
#define TCO2 16
__global__ void __launch_bounds__(224, 2)
k_conv2() {
    __shared__ int sbuf[2][18 * SP];
    const int n   = blockIdx.z;
    const int co0 = blockIdx.y * TCO2;
    const int h0  = blockIdx.x * 16;
    const int h   = h0 + threadIdx.y;
    const int w0  = threadIdx.x * 4;
    const bool act = (h < Hh);
    const int tx  = threadIdx.x;
    const int ty  = threadIdx.y;
    const int tid = ty * 14 + tx;
    const int lane = tid & 31;

    const int* base = g_a1p + (size_t)n * NC4 * HW;

    const int r0  = tid / 14,          cc0 = (tid % 14) * 4;
    const int gr0 = h0 - 1 + r0;
    const bool v0 = (gr0 >= 0) && (gr0 < Hh);
    const bool has1 = (tid < 28);
    const int r1  = (tid + 224) / 14,  cc1 = ((tid + 224) % 14) * 4;
    const int gr1 = h0 - 1 + r1;
    const bool v1 = has1 && (gr1 >= 0) && (gr1 < Hh);

    {
        int4 a = v0 ? __ldg((const int4*)(base + (size_t)gr0 * Ww + cc0))
                    : make_int4(0, 0, 0, 0);
        *(int4*)&sbuf[0][r0 * SP + cc0] = a;
        if (has1) {
            int4 b = v1 ? __ldg((const int4*)(base + (size_t)gr1 * Ww + cc1))
                        : make_int4(0, 0, 0, 0);
            *(int4*)&sbuf[0][r1 * SP + cc1] = b;
        }
    }
    __syncthreads();

    int acc[TCO2][4];
    #pragma unroll
    for (int c = 0; c < TCO2; c++)
        #pragma unroll
        for (int j = 0; j < 4; j++) acc[c][j] = 0;

    #pragma unroll 1
    for (int c4 = 0; c4 < NC4; c4++) {
        const int p = c4 & 1;
        int4 n0 = make_int4(0, 0, 0, 0);
        int4 n1 = make_int4(0, 0, 0, 0);
        if (c4 < NC4 - 1) {
            const int* ip = base + (size_t)(c4 + 1) * HW;
            if (v0) n0 = __ldg((const int4*)(ip + (size_t)gr0 * Ww + cc0));
            if (v1) n1 = __ldg((const int4*)(ip + (size_t)gr1 * Ww + cc1));
        }

        int xv[3][6];
        #pragma unroll
        for (int r = 0; r < 3; r++) {
            const int* sp = &sbuf[p][(ty + r) * SP + w0];
            int4 m = *(const int4*)sp;
            xv[r][1] = m.x; xv[r][2] = m.y; xv[r][3] = m.z; xv[r][4] = m.w;
            xv[r][0] = (tx > 0)  ? sp[-1] : 0;
            xv[r][5] = (tx < 13) ? sp[4]  : 0;
        }

        const int* wp = g_w2p + (c4 * 9) * Cc + co0;
        #pragma unroll
        for (int k = 0; k < 9; k++) {
            const int ky = k / 3, kx = k % 3;
            int4 wa = *(const int4*)(wp + k * Cc + 0);
            int4 wb = *(const int4*)(wp + k * Cc + 4);
            int4 wc = *(const int4*)(wp + k * Cc + 8);
            int4 wd = *(const int4*)(wp + k * Cc + 12);
            int wr[16] = { wa.x, wa.y, wa.z, wa.w, wb.x, wb.y, wb.z, wb.w,
                           wc.x, wc.y, wc.z, wc.w, wd.x, wd.y, wd.z, wd.w };
            #pragma unroll
            for (int c = 0; c < TCO2; c++)
                #pragma unroll
                for (int j = 0; j < 4; j++)
                    acc[c][j] = __dp4a(xv[ky][kx + j], wr[c], acc[c][j]);
        }

        if (c4 < NC4 - 1) {
            *(int4*)&sbuf[p ^ 1][r0 * SP + cc0] = n0;
            if (has1) *(int4*)&sbuf[p ^ 1][r1 * SP + cc1] = n1;
        }
        __syncthreads();
    }

    if (act) {
        #pragma unroll
        for (int c = 0; c < TCO2; c++) {
            float4 v = make_float4((float)acc[c][0], (float)acc[c][1],
                                   (float)acc[c][2], (float)acc[c][3]);
            *(float4*)(g_y2 + (size_t)(n * Cc + co0 + c) * HW + h * Ww + w0) = v;
        }
    } else {
        #pragma unroll
        for (int c = 0; c < TCO2; c++)
            #pragma unroll
            for (int j = 0; j < 4; j++) acc[c][j] = 0;
    }

    __shared__ double wsum[TCO2][7];
    __shared__ double wsq[TCO2][7];
    const int wrp = tid >> 5;
    #pragma unroll
    for (int c = 0; c < TCO2; c++) {
        double s = 0.0, q = 0.0;
        #pragma unroll
        for (int j = 0; j < 4; j++) {
            double v = (double)acc[c][j];
            s += v; q += v * v;
        }
        #pragma unroll
        for (int o = 16; o; o >>= 1) {
            s += __shfl_down_sync(FULLM, s, o);
            q += __shfl_down_sync(FULLM, q, o);
        }
        if (lane == 0) { wsum[c][wrp] = s; wsq[c][wrp] = q; }
    }
    __syncthreads();
    if (tid < TCO2) {
        double s = 0.0, q = 0.0;
        #pragma unroll
        for (int k = 0; k < 7; k++) { s += wsum[tid][k]; q += wsq[tid][k]; }
        atomicAdd(&g_sum[1][co0 + tid], s);
        atomicAdd(&g_sq[1][co0 + tid], q);
    }
}

__global__ void k_stats(int pass) {
    int i = threadIdx.x;
    if (i >= Cc) return;
    double mu = g_sum[pass][i] / (double)NSTAT;
    double e2 = g_sq[pass][i] / (double)NSTAT;
    if (pass == 1) { mu /= 225.0; e2 /= 50625.0; }
    float muf = (float)mu;
    double var = e2 - 2.0 * (double)muf * mu + (double)muf * (double)muf;
    float denom = __fadd_rn((float)var, 1e-5f);
    g_mean[pass][i] = muf;
    g_rs[pass][i]   = (float)(1.0 / sqrt((double)denom));
}

// a1 levels = round(15*clip(bn1(y1),0,1)), packed 4 channels/int32
__global__ void k_bnq(const float* __restrict__ gamma,
                      const float* __restrict__ beta) {
    int p = blockIdx.x * blockDim.x + threadIdx.x;
    if (p >= NTOT / 16) return;
    const int pix4 = p % (HW / 4);
    const int c4   = (p / (HW / 4)) % NC4;
    const int n    = p / (HW / 4) / NC4;
    const int off  = pix4 * 4;

    int out[4] = {0, 0, 0, 0};
    #pragma unroll
    for (int j = 0; j < 4; j++) {
        const int c = c4 * 4 + j;
        const float mean = g_mean[0][c], rs = g_rs[0][c];
        const float gm = gamma[c], bt = beta[c];
        float4 y = *(const float4*)(g_y1 + (size_t)(n * Cc + c) * HW + off);
        float v[4] = { y.x, y.y, y.z, y.w };
        #pragma unroll
        for (int w = 0; w < 4; w++) {
            float xn  = __fmul_rn(__fadd_rn(v[w], -mean), rs);
            float bnv = __fadd_rn(__fmul_rn(xn, gm), bt);
            float cl  = fminf(fmaxf(bnv, 0.0f), 1.0f);
            int lvl   = (int)rintf(__fmul_rn(cl, 15.0f));
            out[w] |= lvl << (8 * j);
        }
    }
    *(int4*)(g_a1p + (size_t)(n * NC4 + c4) * HW + off) =
        make_int4(out[0], out[1], out[2], out[3]);
}

// out = qfn(clip(bn2(acc/225) + x, 0, 1)) with ref STE value semantics
__global__ void k_final(const float* __restrict__ gamma,
                        const float* __restrict__ beta,
                        const float* __restrict__ x,
                        float* __restrict__ outp) {
    size_t i = ((size_t)blockIdx.x * blockDim.x + threadIdx.x) * 4;
    if (i >= (size_t)NTOT) return;
    int c = (int)((i / HW) % Cc);
    const float mean = g_mean[1][c], rs = g_rs[1][c];
    const float gm = gamma[c], bt = beta[c];
    float4 a  = *(const float4*)(g_y2 + i);
    float4 xr = *(const float4*)(x + i);
    float va[4] = { a.x, a.y, a.z, a.w };
    float vx[4] = { xr.x, xr.y, xr.z, xr.w };
    float r[4];
    #pragma unroll
    for (int j = 0; j < 4; j++) {
        float y   = __fdiv_rn(va[j], 225.0f);
        float xn  = __fmul_rn(__fadd_rn(y, -mean), rs);
        float bnv = __fadd_rn(__fmul_rn(xn, gm), bt);
        float vv  = __fadd_rn(bnv, vx[j]);
        float cl  = fminf(fmaxf(vv, 0.0f), 1.0f);
        r[j] = ste_quant(cl);
    }
    float4 o; o.x = r[0]; o.y = r[1]; o.z = r[2]; o.w = r[3];
    *(float4*)(outp + i) = o;
}

// ---------------- launch ----------------
extern "C" void kernel_launch(void* const* d_in, const int* in_sizes, int n_in,
                              void* d_out, int out_size) {
    const float* x      = (const float*)d_in[0];
    const float* w1     = (const float*)d_in[1];
    const float* w2     = (const float*)d_in[2];
    const float* gamma1 = (const float*)d_in[3];
    const float* beta1  = (const float*)d_in[4];
    const float* gamma2 = (const float*)d_in[5];
    const float* beta2  = (const float*)d_in[6];
    float* outp = (float*)d_out;

    k_zero<<<1, 128>>>();

    dim3 wgrid(144, 2);
    k_maxabs<<<wgrid, 256>>>(w1, w2);
    k_quantw<<<wgrid, 256>>>(w1, w2);

    dim3 cblock(14, 16);
    dim3 cgrid1(4, Cc / TCO1, Bn);
    dim3 cgrid2(4, Cc / TCO2, Bn);

    k_conv1<<<cgrid1, cblock>>>(x);
    k_stats<<<1, 128>>>(0);

    const int PB = 256;
    k_bnq<<<(NTOT / 16 + PB - 1) / PB, PB>>>(gamma1, beta1);

    k_conv2<<<cgrid2, cblock>>>();
    k_stats<<<1, 128>>>(1);

    const int EG = (NTOT / 4 + PB - 1) / PB;
    k_final<<<EG, PB>>>(gamma2, beta2, x, outp);
}

// round 14
// speedup vs baseline: 1.1871x; 1.1871x over previous
#include <cuda_runtime.h>
#include <math.h>
#include <stdint.h>

// Problem constants
#define Bn   64
#define Cc   128
#define Hh   56
#define Ww   56
#define HW   3136            // Hh*Ww
#define NTOT 25690112        // Bn*Cc*HW
#define WN   147456          // Cc*Cc*9
#define NSTAT 200704         // Bn*HW
#define NC4  32              // Cc/4
#define FULLM 0xffffffffu

// ---------------- device scratch ----------------
__device__ float   g_qw1[WN];        // conv1 fp32 quantized weights [ci][k][co]
__device__ int     g_w2p[NC4*9*Cc];  // conv2 s8 weights packed [ci4][k][co][4]
__device__ float   g_y1[NTOT];       // conv1 raw output
__device__ int     g_a1p[NTOT/4];    // a1 int levels packed [n][ci4][h][w][4]
__device__ float   g_y2[NTOT];       // conv2 integer accumulator (exact in fp32)
__device__ double  g_sum[2][Cc];
__device__ double  g_sq[2][Cc];
__device__ float   g_mean[2][Cc];
__device__ float   g_rs[2][Cc];
__device__ unsigned g_maxbits[2];

// ---------------- math helpers ----------------
__device__ __forceinline__ float xla_tanh(float x) {
    if (fabsf(x) < 0.0004f) return x;
    float xc = fminf(fmaxf(x, -7.90531110763549805f), 7.90531110763549805f);
    float x2 = __fmul_rn(xc, xc);
    float np = -2.76076847742355e-16f;
    np = fmaf(np, x2, 2.00018790482477e-13f);
    np = fmaf(np, x2, -8.60467152213735e-11f);
    np = fmaf(np, x2, 5.12229709037114e-08f);
    np = fmaf(np, x2, 1.48572235717979e-05f);
    np = fmaf(np, x2, 6.37261928875436e-04f);
    np = fmaf(np, x2, 4.89352455891786e-03f);
    np = __fmul_rn(xc, np);
    float dp = 1.19825839466702e-06f;
    dp = fmaf(dp, x2, 1.18534705686654e-04f);
    dp = fmaf(dp, x2, 2.26843463243900e-03f);
    dp = fmaf(dp, x2, 4.89352518554385e-03f);
    return __fdiv_rn(np, dp);
}
__device__ __forceinline__ float ste_quant(float c) {
    float q = __fdiv_rn(rintf(__fmul_rn(c, 15.0f)), 15.0f);
    return __fadd_rn(c, __fadd_rn(q, -c));
}

// ---------------- kernels ----------------
__global__ void k_zero() {
    int i = threadIdx.x;
    if (i < Cc) { g_sum[0][i]=0.0; g_sum[1][i]=0.0; g_sq[0][i]=0.0; g_sq[1][i]=0.0; }
    if (i < 2) g_maxbits[i] = 0u;
}

__global__ void k_maxabs(const float* __restrict__ w1,
                         const float* __restrict__ w2) {
    const int t = blockIdx.y;
    const float* w = t ? w2 : w1;
    float m = 0.0f;
    for (int i = blockIdx.x * blockDim.x + threadIdx.x; i < WN;
         i += gridDim.x * blockDim.x)
        m = fmaxf(m, fabsf(xla_tanh(w[i])));
    #pragma unroll
    for (int o = 16; o; o >>= 1) m = fmaxf(m, __shfl_xor_sync(FULLM, m, o));
    if ((threadIdx.x & 31) == 0) atomicMax(&g_maxbits[t], __float_as_uint(m));
}

__global__ void k_quantw(const float* __restrict__ w1,
                         const float* __restrict__ w2) {
    const int t = blockIdx.y;
    const float* w = t ? w2 : w1;
    const float M = __uint_as_float(g_maxbits[t]);
    const float twoM = __fmul_rn(2.0f, M);
    for (int i = blockIdx.x * blockDim.x + threadIdx.x; i < WN;
         i += gridDim.x * blockDim.x) {
        float tv = xla_tanh(w[i]);
        float wn = __fadd_rn(__fdiv_rn(tv, twoM), 0.5f);
        int k = i % 9, ci = (i / 9) % Cc, co = i / (9 * Cc);
        if (t == 0) {
            float st = ste_quant(wn);
            float ov = __fadd_rn(__fmul_rn(2.0f, st), -1.0f);
            g_qw1[(ci * 9 + k) * Cc + co] = ov;
        } else {
            int lvl = (int)rintf(__fmul_rn(wn, 15.0f));
            signed char v = (signed char)(2 * lvl - 15);
            ((signed char*)g_w2p)[(((ci >> 2) * 9 + k) * Cc + co) * 4 + (ci & 3)] = v;
        }
    }
}

// window loader: identical values to R10 (1 aligned float4 + 2 scalars per row)
__device__ __forceinline__ void load_win(const float* __restrict__ ip,
                                         int h, int w0,
                                         bool r0ok, bool r2ok, bool c0ok, bool c5ok,
                                         float xv[3][6]) {
    #pragma unroll
    for (int r = 0; r < 3; r++) {
        const int hh = h - 1 + r;
        const bool rok = (r == 0) ? r0ok : ((r == 2) ? r2ok : true);
        const float* rowp = ip + hh * Ww;
        float4 m = rok ? __ldg((const float4*)(rowp + w0))
                       : make_float4(0.f, 0.f, 0.f, 0.f);
        xv[r][1] = m.x; xv[r][2] = m.y; xv[r][3] = m.z; xv[r][4] = m.w;
        xv[r][0] = (rok && c0ok) ? __ldg(rowp + w0 - 1) : 0.0f;
        xv[r][5] = (rok && c5ok) ? __ldg(rowp + w0 + 4) : 0.0f;
    }
}

// the 8co x 4px FMA block for one ci (order identical to R5/R10)
__device__ __forceinline__ void fma_block(const float* __restrict__ wp,
                                          const float xv[3][6],
                                          float acc2[8][4]) {
    #pragma unroll
    for (int k = 0; k < 9; k++) {
        const int ky = k / 3, kx = k % 3;
        float4 wa = *(const float4*)(wp + k * Cc + 0);
        float4 wb = *(const float4*)(wp + k * Cc + 4);
        float wr[8] = { wa.x, wa.y, wa.z, wa.w, wb.x, wb.y, wb.z, wb.w };
        #pragma unroll
        for (int c = 0; c < 8; c++)
            #pragma unroll
            for (int j = 0; j < 4; j++)
                acc2[c][j] = fmaf(xv[ky][kx + j], wr[c], acc2[c][j]);
    }
}

// ---------------------------------------------------------------------------
// conv1: fp32 direct 3x3, scalar FFMA, cascaded accumulation (4-ci groups).
// Software-pipelined: window for ci+1 prefetched into registers before the
// FMA block of ci (2-deep rotation, no smem, no shuffles, no syncs).
// Values & FMA order identical to R5/R10 -> bit-identical y1.
// ---------------------------------------------------------------------------
#define TCO1 8
__global__ void __launch_bounds__(224, 2)
k_conv1(const float* __restrict__ xin) {
    const float* __restrict__ wT = g_qw1;
    const int n   = blockIdx.z;
    const int co0 = blockIdx.y * TCO1;
    const int h   = blockIdx.x * 16 + threadIdx.y;
    const int w0  = threadIdx.x * 4;
    const bool act = (h < Hh);

    float accm[TCO1][4], acc2[TCO1][4];
    #pragma unroll
    for (int c = 0; c < TCO1; c++)
        #pragma unroll
        for (int j = 0; j < 4; j++) { accm[c][j] = 0.f; acc2[c][j] = 0.f; }

    if (act) {
        const bool r0ok = (h > 0);
        const bool r2ok = (h < Hh - 1);
        const bool c0ok = (w0 > 0);
        const bool c5ok = (w0 + 4 < Ww);
        const float* base = xin + (size_t)n * Cc * HW;

        float xA[3][6], xB[3][6];
        load_win(base, h, w0, r0ok, r2ok, c0ok, c5ok, xA);

        #pragma unroll 1
        for (int ci = 0; ci < Cc; ci += 2) {
            // prefetch window for ci+1 (overlaps FMAs of ci)
            load_win(base + (size_t)(ci + 1) * HW, h, w0,
                     r0ok, r2ok, c0ok, c5ok, xB);
            fma_block(wT + ci * 9 * Cc + co0, xA, acc2);
            // cascade: flush when ci%4==3 -> here when (ci&3)==2? no:
            // flushes occur after ci values 3,7,... ci here is even; the
            // odd ci (ci+1) below may trigger it.
            if (ci + 2 < Cc)
                load_win(base + (size_t)(ci + 2) * HW, h, w0,
                         r0ok, r2ok, c0ok, c5ok, xA);
            fma_block(wT + (ci + 1) * 9 * Cc + co0, xB, acc2);
            if (((ci + 1) & 3) == 3) {
                #pragma unroll
                for (int c = 0; c < TCO1; c++)
                    #pragma unroll
                    for (int j = 0; j < 4; j++) {
                        accm[c][j] = __fadd_rn(accm[c][j], acc2[c][j]);
                        acc2[c][j] = 0.f;
                    }
            }
        }

        #pragma unroll
        for (int c = 0; c < TCO1; c++) {
            float4 v = make_float4(accm[c][0], accm[c][1], accm[c][2], accm[c][3]);
            *(float4*)(g_y1 + (size_t)(n * Cc + co0 + c) * HW + h * Ww + w0) = v;
        }
    }

    __shared__ double wsum[TCO1][7];
    __shared__ double wsq[TCO1][7];
    const int tid  = threadIdx.y * 14 + threadIdx.x;
    const int lane = tid & 31;
    const int wrp  = tid >> 5;
    #pragma unroll
    for (int c = 0; c < TCO1; c++) {
        double s = 0.0, q = 0.0;
        if (act) {
            #pragma unroll
            for (int j = 0; j < 4; j++) {
                double v = (double)accm[c][j];
                s += v; q += v * v;
            }
        }
        #pragma unroll
        for (int o = 16; o; o >>= 1) {
            s += __shfl_down_sync(FULLM, s, o);
            q += __shfl_down_sync(FULLM, q, o);
        }
        if (lane == 0) { wsum[c][wrp] = s; wsq[c][wrp] = q; }
    }
    __syncthreads();
    if (tid < TCO1) {
        double s = 0.0, q = 0.0;
        #pragma unroll
        for (int k = 0; k < 7; k++) { s += wsum[tid][k]; q += wsq[tid][k]; }
        atomicAdd(&g_sum[0][co0 + tid], s);
        atomicAdd(&g_sq[0][co0 + tid], q);
    }
}

// ---------------------------------------------------------------------------
// conv2: EXACT int8 dp4a conv (R10 version, at its dp4a issue floor).
// ---------------------------------------------------------------------------
#define TCO2 16
__global__ void __launch_bounds__(224, 2)
k_conv2() {
    const int n   = blockIdx.z;
    const int co0 = blockIdx.y * TCO2;
    const int h   = blockIdx.x * 16 + threadIdx.y;
    const int w0  = threadIdx.x * 4;
    const bool act = (h < Hh);

    int acc[TCO2][4];
    #pragma unroll
    for (int c = 0; c < TCO2; c++)
        #pragma unroll
        for (int j = 0; j < 4; j++) acc[c][j] = 0;

    if (act) {
        const bool r0ok = (h > 0), r2ok = (h < Hh - 1);
        const bool c0ok = (w0 > 0), c5ok = (w0 + 4 < Ww);
        const int* base = g_a1p + (size_t)n * NC4 * HW;

        #pragma unroll 1
        for (int c4 = 0; c4 < NC4; c4++) {
            const int* ip = base + (size_t)c4 * HW;
            int xv[3][6];
            #pragma unroll
            for (int r = 0; r < 3; r++) {
                const int hh = h - 1 + r;
                const bool rok = (r == 0) ? r0ok : ((r == 2) ? r2ok : true);
                const int* rowp = ip + hh * Ww;
                int4 m = rok ? __ldg((const int4*)(rowp + w0)) : make_int4(0, 0, 0, 0);
                xv[r][1] = m.x; xv[r][2] = m.y; xv[r][3] = m.z; xv[r][4] = m.w;
                xv[r][0] = (rok && c0ok) ? __ldg(rowp + w0 - 1) : 0;
                xv[r][5] = (rok && c5ok) ? __ldg(rowp + w0 + 4) : 0;
            }
            const int* wp = g_w2p + (c4 * 9) * Cc + co0;
            #pragma unroll
            for (int k = 0; k < 9; k++) {
                const int ky = k / 3, kx = k % 3;
                int4 wa = *(const int4*)(wp + k * Cc + 0);
                int4 wb = *(const int4*)(wp + k * Cc + 4);
                int4 wc = *(const int4*)(wp + k * Cc + 8);
                int4 wd = *(const int4*)(wp + k * Cc + 12);
                int wr[16] = { wa.x, wa.y, wa.z, wa.w, wb.x, wb.y, wb.z, wb.w,
                               wc.x, wc.y, wc.z, wc.w, wd.x, wd.y, wd.z, wd.w };
                #pragma unroll
                for (int c = 0; c < TCO2; c++)
                    #pragma unroll
                    for (int j = 0; j < 4; j++)
                        acc[c][j] = __dp4a(xv[ky][kx + j], wr[c], acc[c][j]);
            }
        }

        #pragma unroll
        for (int c = 0; c < TCO2; c++) {
            float4 v = make_float4((float)acc[c][0], (float)acc[c][1],
                                   (float)acc[c][2], (float)acc[c][3]);
            *(float4*)(g_y2 + (size_t)(n * Cc + co0 + c) * HW + h * Ww + w0) = v;
        }
    }

    __shared__ double wsum[TCO2][7];
    __shared__ double wsq[TCO2][7];
    const int tid = threadIdx.y * 14 + threadIdx.x;
    const int lane = tid & 31, wrp = tid >> 5;
    #pragma unroll
    for (int c = 0; c < TCO2; c++) {
        double s = 0.0, q = 0.0;
        if (act) {
            #pragma unroll
            for (int j = 0; j < 4; j++) {
                double v = (double)acc[c][j];
                s += v; q += v * v;
            }
        }
        #pragma unroll
        for (int o = 16; o; o >>= 1) {
            s += __shfl_down_sync(FULLM, s, o);
            q += __shfl_down_sync(FULLM, q, o);
        }
        if (lane == 0) { wsum[c][wrp] = s; wsq[c][wrp] = q; }
    }
    __syncthreads();
    if (tid < TCO2) {
        double s = 0.0, q = 0.0;
        #pragma unroll
        for (int k = 0; k < 7; k++) { s += wsum[tid][k]; q += wsq[tid][k]; }
        atomicAdd(&g_sum[1][co0 + tid], s);
        atomicAdd(&g_sq[1][co0 + tid], q);
    }
}

__global__ void k_stats(int pass) {
    int i = threadIdx.x;
    if (i >= Cc) return;
    double mu = g_sum[pass][i] / (double)NSTAT;
    double e2 = g_sq[pass][i] / (double)NSTAT;
    if (pass == 1) { mu /= 225.0; e2 /= 50625.0; }
    float muf = (float)mu;
    double var = e2 - 2.0 * (double)muf * mu + (double)muf * (double)muf;
    float denom = __fadd_rn((float)var, 1e-5f);
    g_mean[pass][i] = muf;
    g_rs[pass][i]   = (float)(1.0 / sqrt((double)denom));
}

// a1 levels = round(15*clip(bn1(y1),0,1)), packed 4 channels/int32
__global__ void k_bnq(const float* __restrict__ gamma,
                      const float* __restrict__ beta) {
    int p = blockIdx.x * blockDim.x + threadIdx.x;
    if (p >= NTOT / 16) return;
    const int pix4 = p % (HW / 4);
    const int c4   = (p / (HW / 4)) % NC4;
    const int n    = p / (HW / 4) / NC4;
    const int off  = pix4 * 4;

    int out[4] = {0, 0, 0, 0};
    #pragma unroll
    for (int j = 0; j < 4; j++) {
        const int c = c4 * 4 + j;
        const float mean = g_mean[0][c], rs = g_rs[0][c];
        const float gm = gamma[c], bt = beta[c];
        float4 y = *(const float4*)(g_y1 + (size_t)(n * Cc + c) * HW + off);
        float v[4] = { y.x, y.y, y.z, y.w };
        #pragma unroll
        for (int w = 0; w < 4; w++) {
            float xn  = __fmul_rn(__fadd_rn(v[w], -mean), rs);
            float bnv = __fadd_rn(__fmul_rn(xn, gm), bt);
            float cl  = fminf(fmaxf(bnv, 0.0f), 1.0f);
            int lvl   = (int)rintf(__fmul_rn(cl, 15.0f));
            out[w] |= lvl << (8 * j);
        }
    }
    *(int4*)(g_a1p + (size_t)(n * NC4 + c4) * HW + off) =
        make_int4(out[0], out[1], out[2], out[3]);
}

// out = qfn(clip(bn2(acc/225) + x, 0, 1)) with ref STE value semantics
__global__ void k_final(const float* __restrict__ gamma,
                        const float* __restrict__ beta,
                        const float* __restrict__ x,
                        float* __restrict__ outp) {
    size_t i = ((size_t)blockIdx.x * blockDim.x + threadIdx.x) * 4;
    if (i >= (size_t)NTOT) return;
    int c = (int)((i / HW) % Cc);
    const float mean = g_mean[1][c], rs = g_rs[1][c];
    const float gm = gamma[c], bt = beta[c];
    float4 a  = *(const float4*)(g_y2 + i);
    float4 xr = *(const float4*)(x + i);
    float va[4] = { a.x, a.y, a.z, a.w };
    float vx[4] = { xr.x, xr.y, xr.z, xr.w };
    float r[4];
    #pragma unroll
    for (int j = 0; j < 4; j++) {
        float y   = __fdiv_rn(va[j], 225.0f);
        float xn  = __fmul_rn(__fadd_rn(y, -mean), rs);
        float bnv = __fadd_rn(__fmul_rn(xn, gm), bt);
        float vv  = __fadd_rn(bnv, vx[j]);
        float cl  = fminf(fmaxf(vv, 0.0f), 1.0f);
        r[j] = ste_quant(cl);
    }
    float4 o; o.x = r[0]; o.y = r[1]; o.z = r[2]; o.w = r[3];
    *(float4*)(outp + i) = o;
}

// ---------------- launch ----------------
extern "C" void kernel_launch(void* const* d_in, const int* in_sizes, int n_in,
                              void* d_out, int out_size) {
    const float* x      = (const float*)d_in[0];
    const float* w1     = (const float*)d_in[1];
    const float* w2     = (const float*)d_in[2];
    const float* gamma1 = (const float*)d_in[3];
    const float* beta1  = (const float*)d_in[4];
    const float* gamma2 = (const float*)d_in[5];
    const float* beta2  = (const float*)d_in[6];
    float* outp = (float*)d_out;

    k_zero<<<1, 128>>>();

    dim3 wgrid(144, 2);
    k_maxabs<<<wgrid, 256>>>(w1, w2);
    k_quantw<<<wgrid, 256>>>(w1, w2);

    dim3 cblock(14, 16);
    dim3 cgrid1(4, Cc / TCO1, Bn);
    dim3 cgrid2(4, Cc / TCO2, Bn);

    k_conv1<<<cgrid1, cblock>>>(x);
    k_stats<<<1, 128>>>(0);

    const int PB = 256;
    k_bnq<<<(NTOT / 16 + PB - 1) / PB, PB>>>(gamma1, beta1);

    k_conv2<<<cgrid2, cblock>>>();
    k_stats<<<1, 128>>>(1);

    const int EG = (NTOT / 4 + PB - 1) / PB;
    k_final<<<EG, PB>>>(gamma2, beta2, x, outp);
}

// round 15
// speedup vs baseline: 1.3099x; 1.1034x over previous
#include <cuda_runtime.h>
#include <math.h>
#include <stdint.h>

// Problem constants
#define Bn   64
#define Cc   128
#define Hh   56
#define Ww   56
#define HW   3136            // Hh*Ww
#define NTOT 25690112        // Bn*Cc*HW
#define WN   147456          // Cc*Cc*9
#define NSTAT 200704         // Bn*HW
#define NC4  32              // Cc/4
#define FULLM 0xffffffffu

// ---------------- device scratch ----------------
__device__ float   g_qw1[WN];        // conv1 fp32 quantized weights [ci][k][co]
__device__ int     g_w2p[NC4*9*Cc];  // conv2 s8 weights packed [ci4][k][co][4]
__device__ float   g_y1[NTOT];       // conv1 raw output
__device__ int     g_a1p[NTOT/4];    // a1 int levels packed [n][ci4][h][w][4]
__device__ float   g_y2[NTOT];       // conv2 integer accumulator (exact in fp32)
__device__ double  g_sum[2][Cc];
__device__ double  g_sq[2][Cc];
__device__ float   g_mean[2][Cc];
__device__ float   g_rs[2][Cc];
__device__ unsigned g_maxbits[2];

// ---------------- packed f32x2 helpers ----------------
__device__ __forceinline__ unsigned long long pk2(float lo, float hi) {
    unsigned long long r;
    asm("mov.b64 %0, {%1, %2};" : "=l"(r)
        : "r"(__float_as_uint(lo)), "r"(__float_as_uint(hi)));
    return r;
}
__device__ __forceinline__ void upk2(unsigned long long v, float& lo, float& hi) {
    uint32_t a, b;
    asm("mov.b64 {%0, %1}, %2;" : "=r"(a), "=r"(b) : "l"(v));
    lo = __uint_as_float(a); hi = __uint_as_float(b);
}
__device__ __forceinline__ unsigned long long fma2(unsigned long long a,
                                                   unsigned long long b,
                                                   unsigned long long c) {
    unsigned long long d;
    asm("fma.rn.f32x2 %0, %1, %2, %3;" : "=l"(d) : "l"(a), "l"(b), "l"(c));
    return d;
}
__device__ __forceinline__ unsigned long long add2(unsigned long long a,
                                                   unsigned long long b) {
    unsigned long long d;
    asm("add.rn.f32x2 %0, %1, %2;" : "=l"(d) : "l"(a), "l"(b));
    return d;
}

// ---------------- math helpers ----------------
__device__ __forceinline__ float xla_tanh(float x) {
    if (fabsf(x) < 0.0004f) return x;
    float xc = fminf(fmaxf(x, -7.90531110763549805f), 7.90531110763549805f);
    float x2 = __fmul_rn(xc, xc);
    float np = -2.76076847742355e-16f;
    np = fmaf(np, x2, 2.00018790482477e-13f);
    np = fmaf(np, x2, -8.60467152213735e-11f);
    np = fmaf(np, x2, 5.12229709037114e-08f);
    np = fmaf(np, x2, 1.48572235717979e-05f);
    np = fmaf(np, x2, 6.37261928875436e-04f);
    np = fmaf(np, x2, 4.89352455891786e-03f);
    np = __fmul_rn(xc, np);
    float dp = 1.19825839466702e-06f;
    dp = fmaf(dp, x2, 1.18534705686654e-04f);
    dp = fmaf(dp, x2, 2.26843463243900e-03f);
    dp = fmaf(dp, x2, 4.89352518554385e-03f);
    return __fdiv_rn(np, dp);
}
__device__ __forceinline__ float ste_quant(float c) {
    float q = __fdiv_rn(rintf(__fmul_rn(c, 15.0f)), 15.0f);
    return __fadd_rn(c, __fadd_rn(q, -c));
}

// ---------------- kernels ----------------
__global__ void k_zero() {
    int i = threadIdx.x;
    if (i < Cc) { g_sum[0][i]=0.0; g_sum[1][i]=0.0; g_sq[0][i]=0.0; g_sq[1][i]=0.0; }
    if (i < 2) g_maxbits[i] = 0u;
}

__global__ void k_maxabs(const float* __restrict__ w1,
                         const float* __restrict__ w2) {
    const int t = blockIdx.y;
    const float* w = t ? w2 : w1;
    float m = 0.0f;
    for (int i = blockIdx.x * blockDim.x + threadIdx.x; i < WN;
         i += gridDim.x * blockDim.x)
        m = fmaxf(m, fabsf(xla_tanh(w[i])));
    #pragma unroll
    for (int o = 16; o; o >>= 1) m = fmaxf(m, __shfl_xor_sync(FULLM, m, o));
    if ((threadIdx.x & 31) == 0) atomicMax(&g_maxbits[t], __float_as_uint(m));
}

__global__ void k_quantw(const float* __restrict__ w1,
                         const float* __restrict__ w2) {
    const int t = blockIdx.y;
    const float* w = t ? w2 : w1;
    const float M = __uint_as_float(g_maxbits[t]);
    const float twoM = __fmul_rn(2.0f, M);
    for (int i = blockIdx.x * blockDim.x + threadIdx.x; i < WN;
         i += gridDim.x * blockDim.x) {
        float tv = xla_tanh(w[i]);
        float wn = __fadd_rn(__fdiv_rn(tv, twoM), 0.5f);
        int k = i % 9, ci = (i / 9) % Cc, co = i / (9 * Cc);
        if (t == 0) {
            float st = ste_quant(wn);
            float ov = __fadd_rn(__fmul_rn(2.0f, st), -1.0f);
            g_qw1[(ci * 9 + k) * Cc + co] = ov;
        } else {
            int lvl = (int)rintf(__fmul_rn(wn, 15.0f));
            signed char v = (signed char)(2 * lvl - 15);
            ((signed char*)g_w2p)[(((ci >> 2) * 9 + k) * Cc + co) * 4 + (ci & 3)] = v;
        }
    }
}

// ---------------------------------------------------------------------------
// conv1: fp32 direct 3x3, f32x2 packed FMAs, cascaded accumulation (4-ci).
// Weight co-pairs are loaded DIRECTLY as 64-bit lanes (ulonglong2) — the pair
// (w[co], w[co+1]) is contiguous in memory, so no mov.b64 packing is needed.
// Bit patterns and FMA order identical to R10 -> bit-identical y1.
// ---------------------------------------------------------------------------
#define TCO1 8
__global__ void __launch_bounds__(224, 2)
k_conv1(const float* __restrict__ xin) {
    const float* __restrict__ wT = g_qw1;
    const int n   = blockIdx.z;
    const int co0 = blockIdx.y * TCO1;
    const int h   = blockIdx.x * 16 + threadIdx.y;
    const int w0  = threadIdx.x * 4;
    const bool act = (h < Hh);

    // acc[copair][j]: packed (co even, co odd) fp32 pairs
    unsigned long long accm[4][4], acc2[4][4];
    #pragma unroll
    for (int cp = 0; cp < 4; cp++)
        #pragma unroll
        for (int j = 0; j < 4; j++) { accm[cp][j] = 0ull; acc2[cp][j] = 0ull; }

    if (act) {
        const bool r0ok = (h > 0);
        const bool r2ok = (h < Hh - 1);
        const bool c0ok = (w0 > 0);
        const bool c5ok = (w0 + 4 < Ww);
        const float* base = xin + (size_t)n * Cc * HW;

        #pragma unroll 1
        for (int ci = 0; ci < Cc; ci++) {
            const float* ip = base + (size_t)ci * HW;
            float xv[3][6];
            #pragma unroll
            for (int r = 0; r < 3; r++) {
                const int hh = h - 1 + r;
                const bool rok = (r == 0) ? r0ok : ((r == 2) ? r2ok : true);
                const float* rowp = ip + hh * Ww;
                float4 m = rok ? __ldg((const float4*)(rowp + w0))
                               : make_float4(0.f, 0.f, 0.f, 0.f);
                xv[r][1] = m.x; xv[r][2] = m.y; xv[r][3] = m.z; xv[r][4] = m.w;
                xv[r][0] = (rok && c0ok) ? __ldg(rowp + w0 - 1) : 0.0f;
                xv[r][5] = (rok && c5ok) ? __ldg(rowp + w0 + 4) : 0.0f;
            }
            // duplicate x values into lane pairs once per ci
            unsigned long long xd[3][6];
            #pragma unroll
            for (int r = 0; r < 3; r++)
                #pragma unroll
                for (int c = 0; c < 6; c++)
                    xd[r][c] = pk2(xv[r][c], xv[r][c]);

            const float* wp = wT + ci * 9 * Cc + co0;
            #pragma unroll
            for (int k = 0; k < 9; k++) {
                const int ky = k / 3, kx = k % 3;
                // direct 64-bit pair loads: (w0,w1),(w2,w3),(w4,w5),(w6,w7)
                ulonglong2 wv0 = *(const ulonglong2*)(wp + k * Cc + 0);
                ulonglong2 wv1 = *(const ulonglong2*)(wp + k * Cc + 4);
                unsigned long long wpair[4] = { wv0.x, wv0.y, wv1.x, wv1.y };
                #pragma unroll
                for (int cp = 0; cp < 4; cp++)
                    #pragma unroll
                    for (int j = 0; j < 4; j++)
                        acc2[cp][j] = fma2(xd[ky][kx + j], wpair[cp], acc2[cp][j]);
            }
            if ((ci & 3) == 3) {   // flush 4-ci group (packed IEEE adds)
                #pragma unroll
                for (int cp = 0; cp < 4; cp++)
                    #pragma unroll
                    for (int j = 0; j < 4; j++) {
                        accm[cp][j] = add2(accm[cp][j], acc2[cp][j]);
                        acc2[cp][j] = 0ull;
                    }
            }
        }
    }

    // unpack accumulators to per-co floats
    float of[TCO1][4];
    #pragma unroll
    for (int cp = 0; cp < 4; cp++)
        #pragma unroll
        for (int j = 0; j < 4; j++)
            upk2(accm[cp][j], of[2 * cp][j], of[2 * cp + 1][j]);

    if (act) {
        #pragma unroll
        for (int c = 0; c < TCO1; c++) {
            float4 v = make_float4(of[c][0], of[c][1], of[c][2], of[c][3]);
            *(float4*)(g_y1 + (size_t)(n * Cc + co0 + c) * HW + h * Ww + w0) = v;
        }
    } else {
        #pragma unroll
        for (int c = 0; c < TCO1; c++)
            #pragma unroll
            for (int j = 0; j < 4; j++) of[c][j] = 0.f;
    }

    __shared__ double wsum[TCO1][7];
    __shared__ double wsq[TCO1][7];
    const int tid  = threadIdx.y * 14 + threadIdx.x;
    const int lane = tid & 31;
    const int wrp  = tid >> 5;
    #pragma unroll
    for (int c = 0; c < TCO1; c++) {
        double s = 0.0, q = 0.0;
        #pragma unroll
        for (int j = 0; j < 4; j++) {
            double v = (double)of[c][j];
            s += v; q += v * v;
        }
        #pragma unroll
        for (int o = 16; o; o >>= 1) {
            s += __shfl_down_sync(FULLM, s, o);
            q += __shfl_down_sync(FULLM, q, o);
        }
        if (lane == 0) { wsum[c][wrp] = s; wsq[c][wrp] = q; }
    }
    __syncthreads();
    if (tid < TCO1) {
        double s = 0.0, q = 0.0;
        #pragma unroll
        for (int k = 0; k < 7; k++) { s += wsum[tid][k]; q += wsq[tid][k]; }
        atomicAdd(&g_sum[0][co0 + tid], s);
        atomicAdd(&g_sq[0][co0 + tid], q);
    }
}

// ---------------------------------------------------------------------------
// conv2: EXACT int8 dp4a conv (unchanged from R10 best).
// ---------------------------------------------------------------------------
#define TCO2 16
__global__ void __launch_bounds__(224, 2)
k_conv2() {
    const int n   = blockIdx.z;
    const int co0 = blockIdx.y * TCO2;
    const int h   = blockIdx.x * 16 + threadIdx.y;
    const int w0  = threadIdx.x * 4;
    const bool act = (h < Hh);

    int acc[TCO2][4];
    #pragma unroll
    for (int c = 0; c < TCO2; c++)
        #pragma unroll
        for (int j = 0; j < 4; j++) acc[c][j] = 0;

    if (act) {
        const bool r0ok = (h > 0), r2ok = (h < Hh - 1);
        const bool c0ok = (w0 > 0), c5ok = (w0 + 4 < Ww);
        const int* base = g_a1p + (size_t)n * NC4 * HW;

        #pragma unroll 1
        for (int c4 = 0; c4 < NC4; c4++) {
            const int* ip = base + (size_t)c4 * HW;
            int xv[3][6];
            #pragma unroll
            for (int r = 0; r < 3; r++) {
                const int hh = h - 1 + r;
                const bool rok = (r == 0) ? r0ok : ((r == 2) ? r2ok : true);
                const int* rowp = ip + hh * Ww;
                int4 m = rok ? __ldg((const int4*)(rowp + w0)) : make_int4(0, 0, 0, 0);
                xv[r][1] = m.x; xv[r][2] = m.y; xv[r][3] = m.z; xv[r][4] = m.w;
                xv[r][0] = (rok && c0ok) ? __ldg(rowp + w0 - 1) : 0;
                xv[r][5] = (rok && c5ok) ? __ldg(rowp + w0 + 4) : 0;
            }
            const int* wp = g_w2p + (c4 * 9) * Cc + co0;
            #pragma unroll
            for (int k = 0; k < 9; k++) {
                const int ky = k / 3, kx = k % 3;
                int4 wa = *(const int4*)(wp + k * Cc + 0);
                int4 wb = *(const int4*)(wp + k * Cc + 4);
                int4 wc = *(const int4*)(wp + k * Cc + 8);
                int4 wd = *(const int4*)(wp + k * Cc + 12);
                int wr[16] = { wa.x, wa.y, wa.z, wa.w, wb.x, wb.y, wb.z, wb.w,
                               wc.x, wc.y, wc.z, wc.w, wd.x, wd.y, wd.z, wd.w };
                #pragma unroll
                for (int c = 0; c < TCO2; c++)
                    #pragma unroll
                    for (int j = 0; j < 4; j++)
                        acc[c][j] = __dp4a(xv[ky][kx + j], wr[c], acc[c][j]);
            }
        }

        #pragma unroll
        for (int c = 0; c < TCO2; c++) {
            float4 v = make_float4((float)acc[c][0], (float)acc[c][1],
                                   (float)acc[c][2], (float)acc[c][3]);
            *(float4*)(g_y2 + (size_t)(n * Cc + co0 + c) * HW + h * Ww + w0) = v;
        }
    }

    __shared__ double wsum[TCO2][7];
    __shared__ double wsq[TCO2][7];
    const int tid = threadIdx.y * 14 + threadIdx.x;
    const int lane = tid & 31, wrp = tid >> 5;
    #pragma unroll
    for (int c = 0; c < TCO2; c++) {
        double s = 0.0, q = 0.0;
        if (act) {
            #pragma unroll
            for (int j = 0; j < 4; j++) {
                double v = (double)acc[c][j];
                s += v; q += v * v;
            }
        }
        #pragma unroll
        for (int o = 16; o; o >>= 1) {
            s += __shfl_down_sync(FULLM, s, o);
            q += __shfl_down_sync(FULLM, q, o);
        }
        if (lane == 0) { wsum[c][wrp] = s; wsq[c][wrp] = q; }
    }
    __syncthreads();
    if (tid < TCO2) {
        double s = 0.0, q = 0.0;
        #pragma unroll
        for (int k = 0; k < 7; k++) { s += wsum[tid][k]; q += wsq[tid][k]; }
        atomicAdd(&g_sum[1][co0 + tid], s);
        atomicAdd(&g_sq[1][co0 + tid], q);
    }
}

__global__ void k_stats(int pass) {
    int i = threadIdx.x;
    if (i >= Cc) return;
    double mu = g_sum[pass][i] / (double)NSTAT;
    double e2 = g_sq[pass][i] / (double)NSTAT;
    if (pass == 1) { mu /= 225.0; e2 /= 50625.0; }
    float muf = (float)mu;
    double var = e2 - 2.0 * (double)muf * mu + (double)muf * (double)muf;
    float denom = __fadd_rn((float)var, 1e-5f);
    g_mean[pass][i] = muf;
    g_rs[pass][i]   = (float)(1.0 / sqrt((double)denom));
}

// a1 levels = round(15*clip(bn1(y1),0,1)), packed 4 channels/int32
__global__ void k_bnq(const float* __restrict__ gamma,
                      const float* __restrict__ beta) {
    int p = blockIdx.x * blockDim.x + threadIdx.x;
    if (p >= NTOT / 16) return;
    const int pix4 = p % (HW / 4);
    const int c4   = (p / (HW / 4)) % NC4;
    const int n    = p / (HW / 4) / NC4;
    const int off  = pix4 * 4;

    int out[4] = {0, 0, 0, 0};
    #pragma unroll
    for (int j = 0; j < 4; j++) {
        const int c = c4 * 4 + j;
        const float mean = g_mean[0][c], rs = g_rs[0][c];
        const float gm = gamma[c], bt = beta[c];
        float4 y = *(const float4*)(g_y1 + (size_t)(n * Cc + c) * HW + off);
        float v[4] = { y.x, y.y, y.z, y.w };
        #pragma unroll
        for (int w = 0; w < 4; w++) {
            float xn  = __fmul_rn(__fadd_rn(v[w], -mean), rs);
            float bnv = __fadd_rn(__fmul_rn(xn, gm), bt);
            float cl  = fminf(fmaxf(bnv, 0.0f), 1.0f);
            int lvl   = (int)rintf(__fmul_rn(cl, 15.0f));
            out[w] |= lvl << (8 * j);
        }
    }
    *(int4*)(g_a1p + (size_t)(n * NC4 + c4) * HW + off) =
        make_int4(out[0], out[1], out[2], out[3]);
}

// out = qfn(clip(bn2(acc/225) + x, 0, 1)) with ref STE value semantics
__global__ void k_final(const float* __restrict__ gamma,
                        const float* __restrict__ beta,
                        const float* __restrict__ x,
                        float* __restrict__ outp) {
    size_t i = ((size_t)blockIdx.x * blockDim.x + threadIdx.x) * 4;
    if (i >= (size_t)NTOT) return;
    int c = (int)((i / HW) % Cc);
    const float mean = g_mean[1][c], rs = g_rs[1][c];
    const float gm = gamma[c], bt = beta[c];
    float4 a  = *(const float4*)(g_y2 + i);
    float4 xr = *(const float4*)(x + i);
    float va[4] = { a.x, a.y, a.z, a.w };
    float vx[4] = { xr.x, xr.y, xr.z, xr.w };
    float r[4];
    #pragma unroll
    for (int j = 0; j < 4; j++) {
        float y   = __fdiv_rn(va[j], 225.0f);
        float xn  = __fmul_rn(__fadd_rn(y, -mean), rs);
        float bnv = __fadd_rn(__fmul_rn(xn, gm), bt);
        float vv  = __fadd_rn(bnv, vx[j]);
        float cl  = fminf(fmaxf(vv, 0.0f), 1.0f);
        r[j] = ste_quant(cl);
    }
    float4 o; o.x = r[0]; o.y = r[1]; o.z = r[2]; o.w = r[3];
    *(float4*)(outp + i) = o;
}

// ---------------- launch ----------------
extern "C" void kernel_launch(void* const* d_in, const int* in_sizes, int n_in,
                              void* d_out, int out_size) {
    const float* x      = (const float*)d_in[0];
    const float* w1     = (const float*)d_in[1];
    const float* w2     = (const float*)d_in[2];
    const float* gamma1 = (const float*)d_in[3];
    const float* beta1  = (const float*)d_in[4];
    const float* gamma2 = (const float*)d_in[5];
    const float* beta2  = (const float*)d_in[6];
    float* outp = (float*)d_out;

    k_zero<<<1, 128>>>();

    dim3 wgrid(144, 2);
    k_maxabs<<<wgrid, 256>>>(w1, w2);
    k_quantw<<<wgrid, 256>>>(w1, w2);

    dim3 cblock(14, 16);
    dim3 cgrid1(4, Cc / TCO1, Bn);
    dim3 cgrid2(4, Cc / TCO2, Bn);

    k_conv1<<<cgrid1, cblock>>>(x);
    k_stats<<<1, 128>>>(0);

    const int PB = 256;
    k_bnq<<<(NTOT / 16 + PB - 1) / PB, PB>>>(gamma1, beta1);

    k_conv2<<<cgrid2, cblock>>>();
    k_stats<<<1, 128>>>(1);

    const int EG = (NTOT / 4 + PB - 1) / PB;
    k_final<<<EG, PB>>>(gamma2, beta2, x, outp);
}